// round 10
// baseline (speedup 1.0000x reference)
#include <cuda_runtime.h>

#define KSZ   2
#define CIN   3
#define COUT  16
#define HIN   256
#define WIN   256
#define HF    255
#define WF    255
#define HO    254
#define WO    254
#define BATCH 64
#define NPIX  (BATCH * HF * WF)
#define BN_EPS 1e-5f

#define NTAP  12
#define NTRI  78
#define NSTAT (NTAP + NTRI)
#define CSTR  13            // per-channel constant stride: 12 scaled weights + shift

typedef unsigned long long u64;

__device__ __forceinline__ u64 pk2(float lo, float hi) {
    u64 r; asm("mov.b64 %0,{%1,%2};" : "=l"(r) : "f"(lo), "f"(hi)); return r;
}
__device__ __forceinline__ void up2(u64 v, float& lo, float& hi) {
    asm("mov.b64 {%0,%1},%2;" : "=f"(lo), "=f"(hi) : "l"(v));
}
__device__ __forceinline__ u64 fma2(u64 a, u64 b, u64 c) {
    u64 d; asm("fma.rn.f32x2 %0,%1,%2,%3;" : "=l"(d) : "l"(a), "l"(b), "l"(c)); return d;
}
__device__ __forceinline__ u64 mul2(u64 a, u64 b) {
    u64 d; asm("mul.rn.f32x2 %0,%1,%2;" : "=l"(d) : "l"(a), "l"(b)); return d;
}
__device__ __forceinline__ u64 add2(u64 a, u64 b) {
    u64 d; asm("add.rn.f32x2 %0,%1,%2;" : "=l"(d) : "l"(a), "l"(b)); return d;
}
__device__ __forceinline__ float tha(float x) {
    float y; asm("tanh.approx.f32 %0,%1;" : "=f"(y) : "f"(x)); return y;
}

// ---------------- constant: per-channel [12 x packed w*scale, packed shift] ----------------
__constant__ u64 c_all[COUT * CSTR];

// ---------------- device scratch ----------------
__device__ double g_stat[NSTAT];
__device__ u64    g_all[COUT * CSTR];

// ---------------------------------------------------------------------------
// Kernel 0: zero statistics accumulators
// ---------------------------------------------------------------------------
__global__ void prep_kernel() {
    int t = threadIdx.x;
    if (t < NSTAT) g_stat[t] = 0.0;
}

// ---------------------------------------------------------------------------
// Kernel 1: channel-independent tap sums + Gram matrix (validated).
// ---------------------------------------------------------------------------
__global__ void __launch_bounds__(256, 1) stats_kernel(const float* __restrict__ x) {
    float S[NTAP];
    float G[NTRI];
#pragma unroll
    for (int k = 0; k < NTAP; k++) S[k] = 0.f;
#pragma unroll
    for (int k = 0; k < NTRI; k++) G[k] = 0.f;

    const int stride = gridDim.x * blockDim.x;
    for (int idx = blockIdx.x * blockDim.x + threadIdx.x; idx < NPIX; idx += stride) {
        const int b   = idx / (HF * WF);
        const int rem = idx % (HF * WF);
        const int i   = rem / WF;
        const int j   = rem % WF;
        const float* xb = x + (size_t)b * CIN * HIN * WIN;

        float xv[NTAP];
#pragma unroll
        for (int ci = 0; ci < CIN; ci++) {
            const float* p = xb + (ci * HIN + i) * WIN + j;
            xv[ci * 4 + 0] = __ldg(p);
            xv[ci * 4 + 1] = __ldg(p + 1);
            xv[ci * 4 + 2] = __ldg(p + WIN);
            xv[ci * 4 + 3] = __ldg(p + WIN + 1);
        }
#pragma unroll
        for (int k = 0; k < NTAP; k++) {
            S[k] += xv[k];
#pragma unroll
            for (int l = 0; l <= k; l++)
                G[k * (k + 1) / 2 + l] = fmaf(xv[k], xv[l], G[k * (k + 1) / 2 + l]);
        }
    }

    const unsigned m = 0xffffffffu;
#pragma unroll
    for (int k = 0; k < NTAP; k++) {
        float a = S[k];
#pragma unroll
        for (int o = 16; o > 0; o >>= 1) a += __shfl_xor_sync(m, a, o);
        S[k] = a;
    }
#pragma unroll
    for (int k = 0; k < NTRI; k++) {
        float a = G[k];
#pragma unroll
        for (int o = 16; o > 0; o >>= 1) a += __shfl_xor_sync(m, a, o);
        G[k] = a;
    }

    __shared__ float red[8][NSTAT];
    const int warp = threadIdx.x >> 5, lane = threadIdx.x & 31;
    if (lane == 0) {
#pragma unroll
        for (int k = 0; k < NTAP; k++) red[warp][k] = S[k];
#pragma unroll
        for (int k = 0; k < NTRI; k++) red[warp][NTAP + k] = G[k];
    }
    __syncthreads();
    if (threadIdx.x < NSTAT) {
        float tot = 0.f;
#pragma unroll
        for (int w = 0; w < 8; w++) tot += red[w][threadIdx.x];
        atomicAdd(&g_stat[threadIdx.x], (double)tot);
    }
}

// ---------------------------------------------------------------------------
// Kernel 2: reconstruct per-channel stats, fold BN, pack scaled weights +
// shift per channel (conv bias cancels under train-mode BN).
// ---------------------------------------------------------------------------
__global__ void finalize_kernel(const float* __restrict__ w,
                                const float* __restrict__ gamma,
                                const float* __restrict__ beta) {
    int c = threadIdx.x;
    if (c >= COUT) return;
    const double N = (double)NPIX;
    double wc[NTAP];
#pragma unroll
    for (int k = 0; k < NTAP; k++) wc[k] = (double)w[c * NTAP + k];

    double mean = 0.0;
#pragma unroll
    for (int k = 0; k < NTAP; k++) mean += wc[k] * g_stat[k];
    mean /= N;

    double e2 = 0.0;
#pragma unroll
    for (int k = 0; k < NTAP; k++) {
#pragma unroll
        for (int l = 0; l <= k; l++) {
            double g = g_stat[NTAP + k * (k + 1) / 2 + l];
            double t = wc[k] * wc[l] * g;
            e2 += (l == k) ? t : 2.0 * t;
        }
    }
    e2 /= N;
    double var = e2 - mean * mean;
    float scale = gamma[c] * rsqrtf((float)var + BN_EPS);
    float shift = beta[c] - (float)mean * scale;
#pragma unroll
    for (int k = 0; k < NTAP; k++) {
        float ws = w[c * NTAP + k] * scale;
        g_all[c * CSTR + k] = pk2(ws, ws);
    }
    g_all[c * CSTR + NTAP] = pk2(shift, shift);
}

// ---------------------------------------------------------------------------
// Kernel 3: fused conv+BN+relu+tanh+window. Packed f32x2, LDCU weights.
// NEW mapping: warp -> 4-pair column group, lane -> row strip. In the x-
// overhang tile, warps whose whole column group is >= WF skip the conv
// loop entirely (cuts the 18% tile-overhang waste).
// ---------------------------------------------------------------------------
__global__ void __launch_bounds__(256, 4) fused_out_kernel(const float* __restrict__ x,
                                                           float* __restrict__ out) {
    __shared__ u64 s_pe[CIN][17][33];   // (x[2j], x[2j+1]) pairs, col 32 = next pair
    __shared__ u64 s_st[16][33];        // packed tanh sums

    const int tid = threadIdx.x;
    const int b   = blockIdx.z;
    const int oy0 = blockIdx.y * 15;
    const int ox0 = blockIdx.x * 62;

    // even pairs from gmem (aligned LDG.64, coalesced)
    const float* xb = x + (size_t)b * CIN * HIN * WIN;
    for (int idx = tid; idx < CIN * 17 * 33; idx += 256) {
        const int jc = idx % 33;
        const int t2 = idx / 33;
        const int r  = t2 % 17;
        const int ci = t2 / 17;
        const int gr = oy0 + r, gc = ox0 + 2 * jc;
        u64 v = 0ull;
        if (gr < HIN && gc < WIN)
            v = *(const u64*)&xb[(size_t)(ci * HIN + gr) * WIN + gc];
        s_pe[ci][r][jc] = v;
    }
    __syncthreads();

    // warp -> column group, lane -> row strip
    const int warp = tid >> 5;
    const int lane = tid & 31;
    const int jp   = 4 * warp + (lane & 3);     // pair-column 0..31
    const int r0   = 2 * (lane >> 2);           // feat rows r0, r0+1

    // warp-uniform skip: whole column group beyond last feat column
    const bool wactive = (ox0 + 8 * warp) < WF;

    if (wactive) {
        u64 e[CIN][3], o[CIN][3];
#pragma unroll
        for (int ci = 0; ci < CIN; ci++) {
#pragma unroll
            for (int i = 0; i < 3; i++) {
                u64 ev = s_pe[ci][r0 + i][jp];
                u64 en = s_pe[ci][r0 + i][jp + 1];
                float elo, ehi, nlo, nhi;
                up2(ev, elo, ehi); up2(en, nlo, nhi);
                e[ci][i] = ev;
                o[ci][i] = pk2(ehi, nlo);
            }
        }

        float accA[2], accB[2];
        accA[0] = accA[1] = accB[0] = accB[1] = 0.f;

#pragma unroll 1
        for (int c = 0; c < COUT; c++) {
            const u64* w = &c_all[c * CSTR];      // warp-uniform -> LDCU/UR
            const u64 sh = w[NTAP];
#pragma unroll
            for (int i = 0; i < 2; i++) {
                u64 v0 = fma2(w[0], e[0][i], sh);     // shift folded into chain init
                v0 = fma2(w[1],  o[0][i],     v0);
                v0 = fma2(w[2],  e[0][i + 1], v0);
                v0 = fma2(w[3],  o[0][i + 1], v0);
                v0 = fma2(w[4],  e[1][i],     v0);
                v0 = fma2(w[5],  o[1][i],     v0);
                u64 v1 = mul2(w[6], e[1][i + 1]);
                v1 = fma2(w[7],  o[1][i + 1], v1);
                v1 = fma2(w[8],  e[2][i],     v1);
                v1 = fma2(w[9],  o[2][i],     v1);
                v1 = fma2(w[10], e[2][i + 1], v1);
                v1 = fma2(w[11], o[2][i + 1], v1);
                u64 v = add2(v0, v1);
                float lo, hi; up2(v, lo, hi);
                accA[i] += tha(fmaxf(lo, 0.f));
                accB[i] += tha(fmaxf(hi, 0.f));
            }
        }
        s_st[r0 + 0][jp] = pk2(accA[0], accB[0]);
        s_st[r0 + 1][jp] = pk2(accA[1], accB[1]);
    }
    __syncthreads();

    // 2x2 window mean (float view, row stride 66); only in-range outputs
    // are read, so skipped warps' unwritten s_st cells are never touched.
    const float* stf = (const float*)s_st;
    const float inv = 1.0f / (COUT * KSZ * KSZ);
    for (int p = tid; p < 62 * 15; p += 256) {
        const int oy = p / 62, ox_ = p - oy * 62;
        const int oi = oy0 + oy, oj = ox0 + ox_;
        if (oi < HO && oj < WO) {
            const float* rp = stf + oy * 66 + ox_;
            out[(size_t)(b * HO + oi) * WO + oj] =
                (rp[0] + rp[1] + rp[66] + rp[67]) * inv;
        }
    }
}

// ---------------------------------------------------------------------------
// kernel_launch: inputs: x, conv_w, conv_b (cancels under BN), gamma, beta
// ---------------------------------------------------------------------------
extern "C" void kernel_launch(void* const* d_in, const int* in_sizes, int n_in,
                              void* d_out, int out_size) {
    const float* x      = (const float*)d_in[0];
    const float* conv_w = (const float*)d_in[1];
    const float* gamma  = (const float*)d_in[3];
    const float* beta   = (const float*)d_in[4];
    float* out = (float*)d_out;

    void* p_all = 0;
    cudaGetSymbolAddress(&p_all, g_all);

    prep_kernel<<<1, 96>>>();
    stats_kernel<<<592, 256>>>(x);
    finalize_kernel<<<1, COUT>>>(conv_w, gamma, beta);
    cudaMemcpyToSymbolAsync(c_all, p_all, COUT * CSTR * sizeof(u64),
                            0, cudaMemcpyDeviceToDevice, 0);

    dim3 grid(5, 17, BATCH);   // 62-wide x 15-tall output tiles
    fused_out_kernel<<<grid, 256>>>(x, out);
}

// round 11
// speedup vs baseline: 1.0484x; 1.0484x over previous
#include <cuda_runtime.h>

#define KSZ   2
#define CIN   3
#define COUT  16
#define HIN   256
#define WIN   256
#define HF    255
#define WF    255
#define HO    254
#define WO    254
#define BATCH 64
#define NPIX  (BATCH * HF * WF)
#define BN_EPS 1e-5f

#define NTAP  12
#define NTRI  78
#define NSTAT (NTAP + NTRI)
#define CSTR  13            // per-channel constant stride: 12 scaled weights + shift
#define SROWS 16            // feat rows per stats block

typedef unsigned long long u64;

__device__ __forceinline__ u64 pk2(float lo, float hi) {
    u64 r; asm("mov.b64 %0,{%1,%2};" : "=l"(r) : "f"(lo), "f"(hi)); return r;
}
__device__ __forceinline__ void up2(u64 v, float& lo, float& hi) {
    asm("mov.b64 {%0,%1},%2;" : "=f"(lo), "=f"(hi) : "l"(v));
}
__device__ __forceinline__ u64 fma2(u64 a, u64 b, u64 c) {
    u64 d; asm("fma.rn.f32x2 %0,%1,%2,%3;" : "=l"(d) : "l"(a), "l"(b), "l"(c)); return d;
}
__device__ __forceinline__ u64 mul2(u64 a, u64 b) {
    u64 d; asm("mul.rn.f32x2 %0,%1,%2;" : "=l"(d) : "l"(a), "l"(b)); return d;
}
__device__ __forceinline__ u64 add2(u64 a, u64 b) {
    u64 d; asm("add.rn.f32x2 %0,%1,%2;" : "=l"(d) : "l"(a), "l"(b)); return d;
}
__device__ __forceinline__ float tha(float x) {
    float y; asm("tanh.approx.f32 %0,%1;" : "=f"(y) : "f"(x)); return y;
}

// ---------------- constant: per-channel [12 x packed w*scale, packed shift] ----------------
__constant__ u64 c_all[COUT * CSTR];

// ---------------- device scratch ----------------
__device__ double g_stat[NSTAT];
__device__ u64    g_all[COUT * CSTR];

// ---------------------------------------------------------------------------
// Kernel 0: zero statistics accumulators
// ---------------------------------------------------------------------------
__global__ void prep_kernel() {
    int t = threadIdx.x;
    if (t < NSTAT) g_stat[t] = 0.0;
}

// ---------------------------------------------------------------------------
// Kernel 1: tap sums + Gram matrix, v2.
// Block = 16 feat rows of one image (grid 16 x 64); thread = column j
// walking down rows. No div/mod in the loop; each x row is loaded once
// (bottom) and reused as top for the next feat row: 6 LDG per pixel.
// ---------------------------------------------------------------------------
__global__ void __launch_bounds__(256, 1) stats_kernel(const float* __restrict__ x) {
    float S[NTAP];
    float G[NTRI];
#pragma unroll
    for (int k = 0; k < NTAP; k++) S[k] = 0.f;
#pragma unroll
    for (int k = 0; k < NTRI; k++) G[k] = 0.f;

    const int j  = threadIdx.x;          // 0..255; active j < WF
    const int i0 = blockIdx.x * SROWS;   // first feat row of this block
    const int nr = (i0 + SROWS <= HF) ? SROWS : (HF - i0);
    const float* xb = x + (size_t)blockIdx.y * CIN * HIN * WIN;

    if (j < WF) {
        const float* p0 = xb + (size_t)i0 * WIN + j;
        float t0[CIN], t1[CIN];          // top-row taps (cols j, j+1)
#pragma unroll
        for (int ci = 0; ci < CIN; ci++) {
            const float* p = p0 + (size_t)ci * HIN * WIN;
            t0[ci] = __ldg(p);
            t1[ci] = __ldg(p + 1);
        }
        for (int r = 0; r < nr; r++) {
            const float* pb = p0 + (size_t)(r + 1) * WIN;
            float xv[NTAP];
#pragma unroll
            for (int ci = 0; ci < CIN; ci++) {
                const float* p = pb + (size_t)ci * HIN * WIN;
                float b0 = __ldg(p);
                float b1 = __ldg(p + 1);
                xv[ci * 4 + 0] = t0[ci];
                xv[ci * 4 + 1] = t1[ci];
                xv[ci * 4 + 2] = b0;
                xv[ci * 4 + 3] = b1;
                t0[ci] = b0;             // bottom becomes next row's top
                t1[ci] = b1;
            }
#pragma unroll
            for (int k = 0; k < NTAP; k++) {
                S[k] += xv[k];
#pragma unroll
                for (int l = 0; l <= k; l++)
                    G[k * (k + 1) / 2 + l] = fmaf(xv[k], xv[l], G[k * (k + 1) / 2 + l]);
            }
        }
    }

    const unsigned m = 0xffffffffu;
#pragma unroll
    for (int k = 0; k < NTAP; k++) {
        float a = S[k];
#pragma unroll
        for (int o = 16; o > 0; o >>= 1) a += __shfl_xor_sync(m, a, o);
        S[k] = a;
    }
#pragma unroll
    for (int k = 0; k < NTRI; k++) {
        float a = G[k];
#pragma unroll
        for (int o = 16; o > 0; o >>= 1) a += __shfl_xor_sync(m, a, o);
        G[k] = a;
    }

    __shared__ float red[8][NSTAT];
    const int warp = threadIdx.x >> 5, lane = threadIdx.x & 31;
    if (lane == 0) {
#pragma unroll
        for (int k = 0; k < NTAP; k++) red[warp][k] = S[k];
#pragma unroll
        for (int k = 0; k < NTRI; k++) red[warp][NTAP + k] = G[k];
    }
    __syncthreads();
    if (threadIdx.x < NSTAT) {
        float tot = 0.f;
#pragma unroll
        for (int w = 0; w < 8; w++) tot += red[w][threadIdx.x];
        atomicAdd(&g_stat[threadIdx.x], (double)tot);
    }
}

// ---------------------------------------------------------------------------
// Kernel 2: reconstruct per-channel stats, fold BN, pack scaled weights +
// shift per channel (conv bias cancels under train-mode BN).
// ---------------------------------------------------------------------------
__global__ void finalize_kernel(const float* __restrict__ w,
                                const float* __restrict__ gamma,
                                const float* __restrict__ beta) {
    int c = threadIdx.x;
    if (c >= COUT) return;
    const double N = (double)NPIX;
    double wc[NTAP];
#pragma unroll
    for (int k = 0; k < NTAP; k++) wc[k] = (double)w[c * NTAP + k];

    double mean = 0.0;
#pragma unroll
    for (int k = 0; k < NTAP; k++) mean += wc[k] * g_stat[k];
    mean /= N;

    double e2 = 0.0;
#pragma unroll
    for (int k = 0; k < NTAP; k++) {
#pragma unroll
        for (int l = 0; l <= k; l++) {
            double g = g_stat[NTAP + k * (k + 1) / 2 + l];
            double t = wc[k] * wc[l] * g;
            e2 += (l == k) ? t : 2.0 * t;
        }
    }
    e2 /= N;
    double var = e2 - mean * mean;
    float scale = gamma[c] * rsqrtf((float)var + BN_EPS);
    float shift = beta[c] - (float)mean * scale;
#pragma unroll
    for (int k = 0; k < NTAP; k++) {
        float ws = w[c * NTAP + k] * scale;
        g_all[c * CSTR + k] = pk2(ws, ws);
    }
    g_all[c * CSTR + NTAP] = pk2(shift, shift);
}

// ---------------------------------------------------------------------------
// Kernel 3: fused conv+BN+relu+tanh+window (R9 verbatim — proven 80.5us).
// Packed f32x2; scaled weights + shift via uniform port (LDCU); shift
// folded into chain-0 init; odd pairs built in registers.
// ---------------------------------------------------------------------------
__global__ void __launch_bounds__(256, 4) fused_out_kernel(const float* __restrict__ x,
                                                           float* __restrict__ out) {
    __shared__ u64 s_pe[CIN][17][33];   // (x[2j], x[2j+1]) pairs, col 32 = next pair
    __shared__ u64 s_st[16][33];        // packed tanh sums

    const int tid = threadIdx.x;
    const int b   = blockIdx.z;
    const int oy0 = blockIdx.y * 15;
    const int ox0 = blockIdx.x * 62;

    // even pairs from gmem (aligned LDG.64, coalesced)
    const float* xb = x + (size_t)b * CIN * HIN * WIN;
    for (int idx = tid; idx < CIN * 17 * 33; idx += 256) {
        const int jc = idx % 33;
        const int t2 = idx / 33;
        const int r  = t2 % 17;
        const int ci = t2 / 17;
        const int gr = oy0 + r, gc = ox0 + 2 * jc;
        u64 v = 0ull;
        if (gr < HIN && gc < WIN)
            v = *(const u64*)&xb[(size_t)(ci * HIN + gr) * WIN + gc];
        s_pe[ci][r][jc] = v;
    }
    __syncthreads();

    // strip: pair-col jp, feat rows r0, r0+1; odd pairs built in regs
    const int jp = tid & 31;
    const int r0 = (tid >> 5) * 2;

    u64 e[CIN][3], o[CIN][3];
#pragma unroll
    for (int ci = 0; ci < CIN; ci++) {
#pragma unroll
        for (int i = 0; i < 3; i++) {
            u64 ev = s_pe[ci][r0 + i][jp];
            u64 en = s_pe[ci][r0 + i][jp + 1];
            float elo, ehi, nlo, nhi;
            up2(ev, elo, ehi); up2(en, nlo, nhi);
            e[ci][i] = ev;
            o[ci][i] = pk2(ehi, nlo);
        }
    }

    float accA[2], accB[2];
    accA[0] = accA[1] = accB[0] = accB[1] = 0.f;

#pragma unroll 1
    for (int c = 0; c < COUT; c++) {
        const u64* w = &c_all[c * CSTR];      // warp-uniform -> LDCU/UR
        const u64 sh = w[NTAP];
#pragma unroll
        for (int i = 0; i < 2; i++) {
            u64 v0 = fma2(w[0], e[0][i], sh);     // shift folded into chain init
            v0 = fma2(w[1],  o[0][i],     v0);
            v0 = fma2(w[2],  e[0][i + 1], v0);
            v0 = fma2(w[3],  o[0][i + 1], v0);
            v0 = fma2(w[4],  e[1][i],     v0);
            v0 = fma2(w[5],  o[1][i],     v0);
            u64 v1 = mul2(w[6], e[1][i + 1]);
            v1 = fma2(w[7],  o[1][i + 1], v1);
            v1 = fma2(w[8],  e[2][i],     v1);
            v1 = fma2(w[9],  o[2][i],     v1);
            v1 = fma2(w[10], e[2][i + 1], v1);
            v1 = fma2(w[11], o[2][i + 1], v1);
            u64 v = add2(v0, v1);
            float lo, hi; up2(v, lo, hi);
            accA[i] += tha(fmaxf(lo, 0.f));
            accB[i] += tha(fmaxf(hi, 0.f));
        }
    }
    s_st[r0 + 0][jp] = pk2(accA[0], accB[0]);
    s_st[r0 + 1][jp] = pk2(accA[1], accB[1]);
    __syncthreads();

    // 2x2 window mean (float view, row stride 66)
    const float* stf = (const float*)s_st;
    const float inv = 1.0f / (COUT * KSZ * KSZ);
    for (int p = tid; p < 62 * 15; p += 256) {
        const int oy = p / 62, ox_ = p - oy * 62;
        const int oi = oy0 + oy, oj = ox0 + ox_;
        if (oi < HO && oj < WO) {
            const float* rp = stf + oy * 66 + ox_;
            out[(size_t)(b * HO + oi) * WO + oj] =
                (rp[0] + rp[1] + rp[66] + rp[67]) * inv;
        }
    }
}

// ---------------------------------------------------------------------------
// kernel_launch: inputs: x, conv_w, conv_b (cancels under BN), gamma, beta
// ---------------------------------------------------------------------------
extern "C" void kernel_launch(void* const* d_in, const int* in_sizes, int n_in,
                              void* d_out, int out_size) {
    const float* x      = (const float*)d_in[0];
    const float* conv_w = (const float*)d_in[1];
    const float* gamma  = (const float*)d_in[3];
    const float* beta   = (const float*)d_in[4];
    float* out = (float*)d_out;

    void* p_all = 0;
    cudaGetSymbolAddress(&p_all, g_all);

    prep_kernel<<<1, 96>>>();
    dim3 sgrid((HF + SROWS - 1) / SROWS, BATCH);   // 16 x 64
    stats_kernel<<<sgrid, 256>>>(x);
    finalize_kernel<<<1, COUT>>>(conv_w, gamma, beta);
    cudaMemcpyToSymbolAsync(c_all, p_all, COUT * CSTR * sizeof(u64),
                            0, cudaMemcpyDeviceToDevice, 0);

    dim3 grid(5, 17, BATCH);   // 62-wide x 15-tall output tiles
    fused_out_kernel<<<grid, 256>>>(x, out);
}

// round 12
// speedup vs baseline: 1.1264x; 1.0744x over previous
#include <cuda_runtime.h>

#define KSZ   2
#define CIN   3
#define COUT  16
#define HIN   256
#define WIN   256
#define HF    255
#define WF    255
#define HO    254
#define WO    254
#define BATCH 64
#define NPIX  (BATCH * HF * WF)
#define BN_EPS 1e-5f

#define NTAP  12
#define NTRI  78
#define NSTAT (NTAP + NTRI)
#define CSTR  13            // per-channel constant stride: 12 scaled weights + shift
#define SROWS 16            // feat rows per stats block
#define XB    248           // thin-tile feat column base (outputs 248..253)

typedef unsigned long long u64;

__device__ __forceinline__ u64 pk2(float lo, float hi) {
    u64 r; asm("mov.b64 %0,{%1,%2};" : "=l"(r) : "f"(lo), "f"(hi)); return r;
}
__device__ __forceinline__ void up2(u64 v, float& lo, float& hi) {
    asm("mov.b64 {%0,%1},%2;" : "=f"(lo), "=f"(hi) : "l"(v));
}
__device__ __forceinline__ u64 fma2(u64 a, u64 b, u64 c) {
    u64 d; asm("fma.rn.f32x2 %0,%1,%2,%3;" : "=l"(d) : "l"(a), "l"(b), "l"(c)); return d;
}
__device__ __forceinline__ u64 mul2(u64 a, u64 b) {
    u64 d; asm("mul.rn.f32x2 %0,%1,%2;" : "=l"(d) : "l"(a), "l"(b)); return d;
}
__device__ __forceinline__ u64 add2(u64 a, u64 b) {
    u64 d; asm("add.rn.f32x2 %0,%1,%2;" : "=l"(d) : "l"(a), "l"(b)); return d;
}
__device__ __forceinline__ float tha(float x) {
    float y; asm("tanh.approx.f32 %0,%1;" : "=f"(y) : "f"(x)); return y;
}

// ---------------- constant: per-channel [12 x packed w*scale, packed shift] ----------------
__constant__ u64 c_all[COUT * CSTR];

// ---------------- device scratch (zero-initialized at module load) ----------------
__device__ double g_stat[NSTAT];
__device__ u64    g_all[COUT * CSTR];

// ---------------------------------------------------------------------------
// Kernel 1: tap sums + Gram matrix (validated R11). Accumulates into g_stat;
// finalize_kernel re-zeros g_stat for the next graph replay.
// ---------------------------------------------------------------------------
__global__ void __launch_bounds__(256, 1) stats_kernel(const float* __restrict__ x) {
    float S[NTAP];
    float G[NTRI];
#pragma unroll
    for (int k = 0; k < NTAP; k++) S[k] = 0.f;
#pragma unroll
    for (int k = 0; k < NTRI; k++) G[k] = 0.f;

    const int j  = threadIdx.x;          // 0..255; active j < WF
    const int i0 = blockIdx.x * SROWS;
    const int nr = (i0 + SROWS <= HF) ? SROWS : (HF - i0);
    const float* xb = x + (size_t)blockIdx.y * CIN * HIN * WIN;

    if (j < WF) {
        const float* p0 = xb + (size_t)i0 * WIN + j;
        float t0[CIN], t1[CIN];
#pragma unroll
        for (int ci = 0; ci < CIN; ci++) {
            const float* p = p0 + (size_t)ci * HIN * WIN;
            t0[ci] = __ldg(p);
            t1[ci] = __ldg(p + 1);
        }
        for (int r = 0; r < nr; r++) {
            const float* pb = p0 + (size_t)(r + 1) * WIN;
            float xv[NTAP];
#pragma unroll
            for (int ci = 0; ci < CIN; ci++) {
                const float* p = pb + (size_t)ci * HIN * WIN;
                float b0 = __ldg(p);
                float b1 = __ldg(p + 1);
                xv[ci * 4 + 0] = t0[ci];
                xv[ci * 4 + 1] = t1[ci];
                xv[ci * 4 + 2] = b0;
                xv[ci * 4 + 3] = b1;
                t0[ci] = b0;
                t1[ci] = b1;
            }
#pragma unroll
            for (int k = 0; k < NTAP; k++) {
                S[k] += xv[k];
#pragma unroll
                for (int l = 0; l <= k; l++)
                    G[k * (k + 1) / 2 + l] = fmaf(xv[k], xv[l], G[k * (k + 1) / 2 + l]);
            }
        }
    }

    const unsigned m = 0xffffffffu;
#pragma unroll
    for (int k = 0; k < NTAP; k++) {
        float a = S[k];
#pragma unroll
        for (int o = 16; o > 0; o >>= 1) a += __shfl_xor_sync(m, a, o);
        S[k] = a;
    }
#pragma unroll
    for (int k = 0; k < NTRI; k++) {
        float a = G[k];
#pragma unroll
        for (int o = 16; o > 0; o >>= 1) a += __shfl_xor_sync(m, a, o);
        G[k] = a;
    }

    __shared__ float red[8][NSTAT];
    const int warp = threadIdx.x >> 5, lane = threadIdx.x & 31;
    if (lane == 0) {
#pragma unroll
        for (int k = 0; k < NTAP; k++) red[warp][k] = S[k];
#pragma unroll
        for (int k = 0; k < NTRI; k++) red[warp][NTAP + k] = G[k];
    }
    __syncthreads();
    if (threadIdx.x < NSTAT) {
        float tot = 0.f;
#pragma unroll
        for (int w = 0; w < 8; w++) tot += red[w][threadIdx.x];
        atomicAdd(&g_stat[threadIdx.x], (double)tot);
    }
}

// ---------------------------------------------------------------------------
// Kernel 2: stage stats -> smem, RE-ZERO g_stat (replaces prep_kernel for
// the next graph replay), reconstruct per-channel stats, fold BN.
// ---------------------------------------------------------------------------
__global__ void finalize_kernel(const float* __restrict__ w,
                                const float* __restrict__ gamma,
                                const float* __restrict__ beta) {
    __shared__ double st[NSTAT];
    const int t = threadIdx.x;
    if (t < NSTAT) st[t] = g_stat[t];
    __syncthreads();
    if (t < NSTAT) g_stat[t] = 0.0;     // self-clearing: next replay starts at 0

    if (t >= COUT) return;
    const int c = t;
    const double N = (double)NPIX;
    double wc[NTAP];
#pragma unroll
    for (int k = 0; k < NTAP; k++) wc[k] = (double)w[c * NTAP + k];

    double mean = 0.0;
#pragma unroll
    for (int k = 0; k < NTAP; k++) mean += wc[k] * st[k];
    mean /= N;

    double e2 = 0.0;
#pragma unroll
    for (int k = 0; k < NTAP; k++) {
#pragma unroll
        for (int l = 0; l <= k; l++) {
            double g = st[NTAP + k * (k + 1) / 2 + l];
            double tt = wc[k] * wc[l] * g;
            e2 += (l == k) ? tt : 2.0 * tt;
        }
    }
    e2 /= N;
    double var = e2 - mean * mean;
    float scale = gamma[c] * rsqrtf((float)var + BN_EPS);
    float shift = beta[c] - (float)mean * scale;
#pragma unroll
    for (int k = 0; k < NTAP; k++) {
        float ws = w[c * NTAP + k] * scale;
        g_all[c * CSTR + k] = pk2(ws, ws);
    }
    g_all[c * CSTR + NTAP] = pk2(shift, shift);
}

// ---------------------------------------------------------------------------
// Kernel 3: main fused conv+BN+relu+tanh+window (R9 body, grid.x=4 -> full
// tiles only, outputs 0..247; no x-overhang waste).
// ---------------------------------------------------------------------------
__global__ void __launch_bounds__(256, 4) fused_out_kernel(const float* __restrict__ x,
                                                           float* __restrict__ out) {
    __shared__ u64 s_pe[CIN][17][33];
    __shared__ u64 s_st[16][33];

    const int tid = threadIdx.x;
    const int b   = blockIdx.z;
    const int oy0 = blockIdx.y * 15;
    const int ox0 = blockIdx.x * 62;

    const float* xb = x + (size_t)b * CIN * HIN * WIN;
    for (int idx = tid; idx < CIN * 17 * 33; idx += 256) {
        const int jc = idx % 33;
        const int t2 = idx / 33;
        const int r  = t2 % 17;
        const int ci = t2 / 17;
        const int gr = oy0 + r, gc = ox0 + 2 * jc;
        u64 v = 0ull;
        if (gr < HIN && gc < WIN)
            v = *(const u64*)&xb[(size_t)(ci * HIN + gr) * WIN + gc];
        s_pe[ci][r][jc] = v;
    }
    __syncthreads();

    const int jp = tid & 31;
    const int r0 = (tid >> 5) * 2;

    u64 e[CIN][3], o[CIN][3];
#pragma unroll
    for (int ci = 0; ci < CIN; ci++) {
#pragma unroll
        for (int i = 0; i < 3; i++) {
            u64 ev = s_pe[ci][r0 + i][jp];
            u64 en = s_pe[ci][r0 + i][jp + 1];
            float elo, ehi, nlo, nhi;
            up2(ev, elo, ehi); up2(en, nlo, nhi);
            e[ci][i] = ev;
            o[ci][i] = pk2(ehi, nlo);
        }
    }

    float accA[2], accB[2];
    accA[0] = accA[1] = accB[0] = accB[1] = 0.f;

#pragma unroll 1
    for (int c = 0; c < COUT; c++) {
        const u64* w = &c_all[c * CSTR];
        const u64 sh = w[NTAP];
#pragma unroll
        for (int i = 0; i < 2; i++) {
            u64 v0 = fma2(w[0], e[0][i], sh);
            v0 = fma2(w[1],  o[0][i],     v0);
            v0 = fma2(w[2],  e[0][i + 1], v0);
            v0 = fma2(w[3],  o[0][i + 1], v0);
            v0 = fma2(w[4],  e[1][i],     v0);
            v0 = fma2(w[5],  o[1][i],     v0);
            u64 v1 = mul2(w[6], e[1][i + 1]);
            v1 = fma2(w[7],  o[1][i + 1], v1);
            v1 = fma2(w[8],  e[2][i],     v1);
            v1 = fma2(w[9],  o[2][i],     v1);
            v1 = fma2(w[10], e[2][i + 1], v1);
            v1 = fma2(w[11], o[2][i + 1], v1);
            u64 v = add2(v0, v1);
            float lo, hi; up2(v, lo, hi);
            accA[i] += tha(fmaxf(lo, 0.f));
            accB[i] += tha(fmaxf(hi, 0.f));
        }
    }
    s_st[r0 + 0][jp] = pk2(accA[0], accB[0]);
    s_st[r0 + 1][jp] = pk2(accA[1], accB[1]);
    __syncthreads();

    const float* stf = (const float*)s_st;
    const float inv = 1.0f / (COUT * KSZ * KSZ);
    for (int p = tid; p < 62 * 15; p += 256) {
        const int oy = p / 62, ox_ = p - oy * 62;
        const int oi = oy0 + oy, oj = ox0 + ox_;
        if (oi < HO) {
            const float* rp = stf + oy * 66 + ox_;
            out[(size_t)(b * HO + oi) * WO + oj] =
                (rp[0] + rp[1] + rp[66] + rp[67]) * inv;
        }
    }
}

// ---------------------------------------------------------------------------
// Kernel 4: thin tile, outputs 248..253 (feat cols 248..254). One warp per
// block; same loop body. Independent of kernel 3 -> runs concurrently.
// ---------------------------------------------------------------------------
__global__ void __launch_bounds__(32) fused_thin_kernel(const float* __restrict__ x,
                                                        float* __restrict__ out) {
    __shared__ u64 s_pe[CIN][17][5];   // pairs for cols 248..256 (jc=4 padded)
    __shared__ u64 s_st[16][4];

    const int tid = threadIdx.x;
    const int oy0 = blockIdx.x * 15;
    const int b   = blockIdx.y;

    const float* xb = x + (size_t)b * CIN * HIN * WIN;
    for (int idx = tid; idx < CIN * 17 * 5; idx += 32) {
        const int jc = idx % 5;
        const int t2 = idx / 5;
        const int r  = t2 % 17;
        const int ci = t2 / 17;
        const int gr = oy0 + r, gc = XB + 2 * jc;
        u64 v = 0ull;
        if (gr < HIN && gc < WIN)
            v = *(const u64*)&xb[(size_t)(ci * HIN + gr) * WIN + gc];
        s_pe[ci][r][jc] = v;
    }
    __syncthreads();

    const int jp = tid & 3;            // pair-col 0..3 (feat cols 248..255)
    const int r0 = (tid >> 2) * 2;     // feat rows r0, r0+1

    u64 e[CIN][3], o[CIN][3];
#pragma unroll
    for (int ci = 0; ci < CIN; ci++) {
#pragma unroll
        for (int i = 0; i < 3; i++) {
            u64 ev = s_pe[ci][r0 + i][jp];
            u64 en = s_pe[ci][r0 + i][jp + 1];
            float elo, ehi, nlo, nhi;
            up2(ev, elo, ehi); up2(en, nlo, nhi);
            e[ci][i] = ev;
            o[ci][i] = pk2(ehi, nlo);
        }
    }

    float accA[2], accB[2];
    accA[0] = accA[1] = accB[0] = accB[1] = 0.f;

#pragma unroll 1
    for (int c = 0; c < COUT; c++) {
        const u64* w = &c_all[c * CSTR];
        const u64 sh = w[NTAP];
#pragma unroll
        for (int i = 0; i < 2; i++) {
            u64 v0 = fma2(w[0], e[0][i], sh);
            v0 = fma2(w[1],  o[0][i],     v0);
            v0 = fma2(w[2],  e[0][i + 1], v0);
            v0 = fma2(w[3],  o[0][i + 1], v0);
            v0 = fma2(w[4],  e[1][i],     v0);
            v0 = fma2(w[5],  o[1][i],     v0);
            u64 v1 = mul2(w[6], e[1][i + 1]);
            v1 = fma2(w[7],  o[1][i + 1], v1);
            v1 = fma2(w[8],  e[2][i],     v1);
            v1 = fma2(w[9],  o[2][i],     v1);
            v1 = fma2(w[10], e[2][i + 1], v1);
            v1 = fma2(w[11], o[2][i + 1], v1);
            u64 v = add2(v0, v1);
            float lo, hi; up2(v, lo, hi);
            accA[i] += tha(fmaxf(lo, 0.f));
            accB[i] += tha(fmaxf(hi, 0.f));
        }
    }
    s_st[r0 + 0][jp] = pk2(accA[0], accB[0]);
    s_st[r0 + 1][jp] = pk2(accA[1], accB[1]);
    __syncthreads();

    // outputs 248..253: 6 cols x 15 rows (float view, row stride 8)
    const float* stf = (const float*)s_st;
    const float inv = 1.0f / (COUT * KSZ * KSZ);
    for (int p = tid; p < 6 * 15; p += 32) {
        const int oy = p / 6, ox_ = p - oy * 6;
        const int oi = oy0 + oy, oj = XB + ox_;
        if (oi < HO) {
            const float* rp = stf + oy * 8 + ox_;
            out[(size_t)(b * HO + oi) * WO + oj] =
                (rp[0] + rp[1] + rp[8] + rp[9]) * inv;
        }
    }
}

// ---------------------------------------------------------------------------
// kernel_launch: inputs: x, conv_w, conv_b (cancels under BN), gamma, beta
// ---------------------------------------------------------------------------
extern "C" void kernel_launch(void* const* d_in, const int* in_sizes, int n_in,
                              void* d_out, int out_size) {
    const float* x      = (const float*)d_in[0];
    const float* conv_w = (const float*)d_in[1];
    const float* gamma  = (const float*)d_in[3];
    const float* beta   = (const float*)d_in[4];
    float* out = (float*)d_out;

    void* p_all = 0;
    cudaGetSymbolAddress(&p_all, g_all);

    dim3 sgrid((HF + SROWS - 1) / SROWS, BATCH);   // 16 x 64
    stats_kernel<<<sgrid, 256>>>(x);
    finalize_kernel<<<1, 128>>>(conv_w, gamma, beta);
    cudaMemcpyToSymbolAsync(c_all, p_all, COUT * CSTR * sizeof(u64),
                            0, cudaMemcpyDeviceToDevice, 0);

    dim3 grid(4, 17, BATCH);            // full 62-wide tiles: outputs 0..247
    fused_out_kernel<<<grid, 256>>>(x, out);
    dim3 tgrid(17, BATCH);              // thin tile: outputs 248..253
    fused_thin_kernel<<<tgrid, 32>>>(x, out);
}

// round 13
// speedup vs baseline: 1.1701x; 1.0388x over previous
#include <cuda_runtime.h>

#define KSZ   2
#define CIN   3
#define COUT  16
#define HIN   256
#define WIN   256
#define HF    255
#define WF    255
#define HO    254
#define WO    254
#define BATCH 64
#define NPIX  (BATCH * HF * WF)
#define BN_EPS 1e-5f

#define NTAP  12
#define NTRI  78
#define NSTAT (NTAP + NTRI)
#define CSTR  13            // per-channel constant stride: 12 scaled weights + shift
#define SROWS 16            // feat rows per stats block
#define TPBASE 124          // thin region: pair-columns 124..127 (feat cols 248..255)

typedef unsigned long long u64;

__device__ __forceinline__ u64 pk2(float lo, float hi) {
    u64 r; asm("mov.b64 %0,{%1,%2};" : "=l"(r) : "f"(lo), "f"(hi)); return r;
}
__device__ __forceinline__ void up2(u64 v, float& lo, float& hi) {
    asm("mov.b64 {%0,%1},%2;" : "=f"(lo), "=f"(hi) : "l"(v));
}
__device__ __forceinline__ u64 fma2(u64 a, u64 b, u64 c) {
    u64 d; asm("fma.rn.f32x2 %0,%1,%2,%3;" : "=l"(d) : "l"(a), "l"(b), "l"(c)); return d;
}
__device__ __forceinline__ u64 mul2(u64 a, u64 b) {
    u64 d; asm("mul.rn.f32x2 %0,%1,%2;" : "=l"(d) : "l"(a), "l"(b)); return d;
}
__device__ __forceinline__ u64 add2(u64 a, u64 b) {
    u64 d; asm("add.rn.f32x2 %0,%1,%2;" : "=l"(d) : "l"(a), "l"(b)); return d;
}
__device__ __forceinline__ float tha(float x) {
    float y; asm("tanh.approx.f32 %0,%1;" : "=f"(y) : "f"(x)); return y;
}

// ---------------- constant: per-channel [12 x packed w*scale, packed shift] ----------------
__constant__ u64 c_all[COUT * CSTR];

// ---------------- device scratch (zero-initialized at module load) ----------------
__device__ double g_stat[NSTAT];
__device__ u64    g_all[COUT * CSTR];

// the 16-channel conv+BN+relu+tanh core, shared by both block shapes
__device__ __forceinline__ void conv_core(const u64 e[CIN][3], const u64 o[CIN][3],
                                          float accA[2], float accB[2]) {
#pragma unroll 1
    for (int c = 0; c < COUT; c++) {
        const u64* w = &c_all[c * CSTR];      // warp-uniform -> LDCU/UR
        const u64 sh = w[NTAP];
#pragma unroll
        for (int i = 0; i < 2; i++) {
            u64 v0 = fma2(w[0], e[0][i], sh);     // shift folded into chain init
            v0 = fma2(w[1],  o[0][i],     v0);
            v0 = fma2(w[2],  e[0][i + 1], v0);
            v0 = fma2(w[3],  o[0][i + 1], v0);
            v0 = fma2(w[4],  e[1][i],     v0);
            v0 = fma2(w[5],  o[1][i],     v0);
            u64 v1 = mul2(w[6], e[1][i + 1]);
            v1 = fma2(w[7],  o[1][i + 1], v1);
            v1 = fma2(w[8],  e[2][i],     v1);
            v1 = fma2(w[9],  o[2][i],     v1);
            v1 = fma2(w[10], e[2][i + 1], v1);
            v1 = fma2(w[11], o[2][i + 1], v1);
            u64 v = add2(v0, v1);
            float lo, hi; up2(v, lo, hi);
            accA[i] += tha(fmaxf(lo, 0.f));
            accB[i] += tha(fmaxf(hi, 0.f));
        }
    }
}

// ---------------------------------------------------------------------------
// Kernel 1: tap sums + Gram matrix (validated R11).
// ---------------------------------------------------------------------------
__global__ void __launch_bounds__(256, 1) stats_kernel(const float* __restrict__ x) {
    float S[NTAP];
    float G[NTRI];
#pragma unroll
    for (int k = 0; k < NTAP; k++) S[k] = 0.f;
#pragma unroll
    for (int k = 0; k < NTRI; k++) G[k] = 0.f;

    const int j  = threadIdx.x;
    const int i0 = blockIdx.x * SROWS;
    const int nr = (i0 + SROWS <= HF) ? SROWS : (HF - i0);
    const float* xb = x + (size_t)blockIdx.y * CIN * HIN * WIN;

    if (j < WF) {
        const float* p0 = xb + (size_t)i0 * WIN + j;
        float t0[CIN], t1[CIN];
#pragma unroll
        for (int ci = 0; ci < CIN; ci++) {
            const float* p = p0 + (size_t)ci * HIN * WIN;
            t0[ci] = __ldg(p);
            t1[ci] = __ldg(p + 1);
        }
        for (int r = 0; r < nr; r++) {
            const float* pb = p0 + (size_t)(r + 1) * WIN;
            float xv[NTAP];
#pragma unroll
            for (int ci = 0; ci < CIN; ci++) {
                const float* p = pb + (size_t)ci * HIN * WIN;
                float b0 = __ldg(p);
                float b1 = __ldg(p + 1);
                xv[ci * 4 + 0] = t0[ci];
                xv[ci * 4 + 1] = t1[ci];
                xv[ci * 4 + 2] = b0;
                xv[ci * 4 + 3] = b1;
                t0[ci] = b0;
                t1[ci] = b1;
            }
#pragma unroll
            for (int k = 0; k < NTAP; k++) {
                S[k] += xv[k];
#pragma unroll
                for (int l = 0; l <= k; l++)
                    G[k * (k + 1) / 2 + l] = fmaf(xv[k], xv[l], G[k * (k + 1) / 2 + l]);
            }
        }
    }

    const unsigned m = 0xffffffffu;
#pragma unroll
    for (int k = 0; k < NTAP; k++) {
        float a = S[k];
#pragma unroll
        for (int o = 16; o > 0; o >>= 1) a += __shfl_xor_sync(m, a, o);
        S[k] = a;
    }
#pragma unroll
    for (int k = 0; k < NTRI; k++) {
        float a = G[k];
#pragma unroll
        for (int o = 16; o > 0; o >>= 1) a += __shfl_xor_sync(m, a, o);
        G[k] = a;
    }

    __shared__ float red[8][NSTAT];
    const int warp = threadIdx.x >> 5, lane = threadIdx.x & 31;
    if (lane == 0) {
#pragma unroll
        for (int k = 0; k < NTAP; k++) red[warp][k] = S[k];
#pragma unroll
        for (int k = 0; k < NTRI; k++) red[warp][NTAP + k] = G[k];
    }
    __syncthreads();
    if (threadIdx.x < NSTAT) {
        float tot = 0.f;
#pragma unroll
        for (int w = 0; w < 8; w++) tot += red[w][threadIdx.x];
        atomicAdd(&g_stat[threadIdx.x], (double)tot);
    }
}

// ---------------------------------------------------------------------------
// Kernel 2: stage stats -> smem, re-zero g_stat (for next graph replay),
// reconstruct per-channel stats, fold BN (conv bias cancels).
// ---------------------------------------------------------------------------
__global__ void finalize_kernel(const float* __restrict__ w,
                                const float* __restrict__ gamma,
                                const float* __restrict__ beta) {
    __shared__ double st[NSTAT];
    const int t = threadIdx.x;
    if (t < NSTAT) st[t] = g_stat[t];
    __syncthreads();
    if (t < NSTAT) g_stat[t] = 0.0;

    if (t >= COUT) return;
    const int c = t;
    const double N = (double)NPIX;
    double wc[NTAP];
#pragma unroll
    for (int k = 0; k < NTAP; k++) wc[k] = (double)w[c * NTAP + k];

    double mean = 0.0;
#pragma unroll
    for (int k = 0; k < NTAP; k++) mean += wc[k] * st[k];
    mean /= N;

    double e2 = 0.0;
#pragma unroll
    for (int k = 0; k < NTAP; k++) {
#pragma unroll
        for (int l = 0; l <= k; l++) {
            double g = st[NTAP + k * (k + 1) / 2 + l];
            double tt = wc[k] * wc[l] * g;
            e2 += (l == k) ? tt : 2.0 * tt;
        }
    }
    e2 /= N;
    double var = e2 - mean * mean;
    float scale = gamma[c] * rsqrtf((float)var + BN_EPS);
    float shift = beta[c] - (float)mean * scale;
#pragma unroll
    for (int k = 0; k < NTAP; k++) {
        float ws = w[c * NTAP + k] * scale;
        g_all[c * CSTR + k] = pk2(ws, ws);
    }
    g_all[c * CSTR + NTAP] = pk2(shift, shift);
}

// ---------------------------------------------------------------------------
// Kernel 3: fused conv+BN+relu+tanh+window. Two block shapes in one kernel:
//  by <  17 : main 62x15 output tile (pair-cols 31*bx.., proven R9 body)
//  by >= 17 : (bx==0 only) thin tile, pair-cols 124..127 x 128 feat rows
//             (4 pairs x 64 row-strips = 256 threads, full occupancy)
// ---------------------------------------------------------------------------
__global__ void __launch_bounds__(256, 4) fused_out_kernel(const float* __restrict__ x,
                                                           float* __restrict__ out) {
    __shared__ union {
        struct { u64 pe[CIN][17][33]; u64 st[16][33]; } m;   // main tile
        struct { u64 pe[CIN][129][5]; u64 st[128][4]; } t;   // thin tile
    } sm;

    const int tid = threadIdx.x;
    const int b   = blockIdx.z;
    const float* xb = x + (size_t)b * CIN * HIN * WIN;
    const float inv = 1.0f / (COUT * KSZ * KSZ);

    if (blockIdx.y < 17) {
        // ----------------- main tile (R9 body, outputs 0..247) -----------------
        const int oy0 = blockIdx.y * 15;
        const int ox0 = blockIdx.x * 62;

        for (int idx = tid; idx < CIN * 17 * 33; idx += 256) {
            const int jc = idx % 33;
            const int t2 = idx / 33;
            const int r  = t2 % 17;
            const int ci = t2 / 17;
            const int gr = oy0 + r, gc = ox0 + 2 * jc;
            u64 v = 0ull;
            if (gr < HIN && gc < WIN)
                v = *(const u64*)&xb[(size_t)(ci * HIN + gr) * WIN + gc];
            sm.m.pe[ci][r][jc] = v;
        }
        __syncthreads();

        const int jp = tid & 31;
        const int r0 = (tid >> 5) * 2;

        u64 e[CIN][3], o[CIN][3];
#pragma unroll
        for (int ci = 0; ci < CIN; ci++) {
#pragma unroll
            for (int i = 0; i < 3; i++) {
                u64 ev = sm.m.pe[ci][r0 + i][jp];
                u64 en = sm.m.pe[ci][r0 + i][jp + 1];
                float elo, ehi, nlo, nhi;
                up2(ev, elo, ehi); up2(en, nlo, nhi);
                e[ci][i] = ev;
                o[ci][i] = pk2(ehi, nlo);
            }
        }

        float accA[2] = {0.f, 0.f}, accB[2] = {0.f, 0.f};
        conv_core(e, o, accA, accB);
        sm.m.st[r0 + 0][jp] = pk2(accA[0], accB[0]);
        sm.m.st[r0 + 1][jp] = pk2(accA[1], accB[1]);
        __syncthreads();

        const float* stf = (const float*)sm.m.st;
        for (int p = tid; p < 62 * 15; p += 256) {
            const int oy = p / 62, ox_ = p - oy * 62;
            const int oi = oy0 + oy, oj = ox0 + ox_;
            if (oi < HO) {
                const float* rp = stf + oy * 66 + ox_;
                out[(size_t)(b * HO + oi) * WO + oj] =
                    (rp[0] + rp[1] + rp[66] + rp[67]) * inv;
            }
        }
    } else {
        // ----------------- thin tile (outputs cols 248..253) -----------------
        if (blockIdx.x != 0) return;
        const int oy0 = (blockIdx.y == 17) ? 0 : 127;   // output rows 0..126 / 127..253

        for (int idx = tid; idx < CIN * 129 * 5; idx += 256) {
            const int jc = idx % 5;
            const int t2 = idx / 5;
            const int r  = t2 % 129;
            const int ci = t2 / 129;
            const int gr = oy0 + r, gc = 2 * (TPBASE + jc);
            u64 v = 0ull;
            if (gr < HIN && gc < WIN)
                v = *(const u64*)&xb[(size_t)(ci * HIN + gr) * WIN + gc];
            sm.t.pe[ci][r][jc] = v;
        }
        __syncthreads();

        const int jp = tid & 3;            // pair-col 124+jp
        const int r0 = (tid >> 2) * 2;     // local feat rows r0, r0+1 (0..126)

        u64 e[CIN][3], o[CIN][3];
#pragma unroll
        for (int ci = 0; ci < CIN; ci++) {
#pragma unroll
            for (int i = 0; i < 3; i++) {
                u64 ev = sm.t.pe[ci][r0 + i][jp];
                u64 en = sm.t.pe[ci][r0 + i][jp + 1];
                float elo, ehi, nlo, nhi;
                up2(ev, elo, ehi); up2(en, nlo, nhi);
                e[ci][i] = ev;
                o[ci][i] = pk2(ehi, nlo);
            }
        }

        float accA[2] = {0.f, 0.f}, accB[2] = {0.f, 0.f};
        conv_core(e, o, accA, accB);
        sm.t.st[r0 + 0][jp] = pk2(accA[0], accB[0]);
        sm.t.st[r0 + 1][jp] = pk2(accA[1], accB[1]);
        __syncthreads();

        // outputs: cols 248..253 (6), local rows 0..126 (127)
        const float* stf = (const float*)sm.t.st;
        for (int p = tid; p < 6 * 127; p += 256) {
            const int ly = p / 6, ox_ = p - ly * 6;
            const int oi = oy0 + ly, oj = 2 * TPBASE + ox_;
            const float* rp = stf + ly * 8 + ox_;
            out[(size_t)(b * HO + oi) * WO + oj] =
                (rp[0] + rp[1] + rp[8] + rp[9]) * inv;
        }
    }
}

// ---------------------------------------------------------------------------
// kernel_launch: inputs: x, conv_w, conv_b (cancels under BN), gamma, beta
// ---------------------------------------------------------------------------
extern "C" void kernel_launch(void* const* d_in, const int* in_sizes, int n_in,
                              void* d_out, int out_size) {
    const float* x      = (const float*)d_in[0];
    const float* conv_w = (const float*)d_in[1];
    const float* gamma  = (const float*)d_in[3];
    const float* beta   = (const float*)d_in[4];
    float* out = (float*)d_out;

    void* p_all = 0;
    cudaGetSymbolAddress(&p_all, g_all);

    dim3 sgrid((HF + SROWS - 1) / SROWS, BATCH);   // 16 x 64
    stats_kernel<<<sgrid, 256>>>(x);
    finalize_kernel<<<1, 128>>>(conv_w, gamma, beta);
    cudaMemcpyToSymbolAsync(c_all, p_all, COUT * CSTR * sizeof(u64),
                            0, cudaMemcpyDeviceToDevice, 0);

    dim3 grid(4, 19, BATCH);   // y<17: main 62x15 tiles; y in {17,18}: thin tile
    fused_out_kernel<<<grid, 256>>>(x, out);
}

// round 14
// speedup vs baseline: 1.2195x; 1.0423x over previous
#include <cuda_runtime.h>

#define KSZ   2
#define CIN   3
#define COUT  16
#define HIN   256
#define WIN   256
#define HF    255
#define WF    255
#define HO    254
#define WO    254
#define BATCH 64
#define NPIX  (BATCH * HF * WF)
#define BN_EPS 1e-5f

#define NTAP  12
#define NTRI  78
#define NSTAT (NTAP + NTRI)
#define CSTR  13            // per-channel constant stride: 12 scaled weights + shift
#define SROWS 32            // feat rows per stats block
#define TPBASE 124          // thin region: pair-columns 124..127 (feat cols 248..255)

typedef unsigned long long u64;

__device__ __forceinline__ u64 pk2(float lo, float hi) {
    u64 r; asm("mov.b64 %0,{%1,%2};" : "=l"(r) : "f"(lo), "f"(hi)); return r;
}
__device__ __forceinline__ void up2(u64 v, float& lo, float& hi) {
    asm("mov.b64 {%0,%1},%2;" : "=f"(lo), "=f"(hi) : "l"(v));
}
__device__ __forceinline__ u64 fma2(u64 a, u64 b, u64 c) {
    u64 d; asm("fma.rn.f32x2 %0,%1,%2,%3;" : "=l"(d) : "l"(a), "l"(b), "l"(c)); return d;
}
__device__ __forceinline__ u64 mul2(u64 a, u64 b) {
    u64 d; asm("mul.rn.f32x2 %0,%1,%2;" : "=l"(d) : "l"(a), "l"(b)); return d;
}
__device__ __forceinline__ u64 add2(u64 a, u64 b) {
    u64 d; asm("add.rn.f32x2 %0,%1,%2;" : "=l"(d) : "l"(a), "l"(b)); return d;
}
__device__ __forceinline__ float tha(float x) {
    float y; asm("tanh.approx.f32 %0,%1;" : "=f"(y) : "f"(x)); return y;
}

// ---------------- constant: per-channel [12 x packed w*scale, packed shift] ----------------
__constant__ u64 c_all[COUT * CSTR];

// ---------------- device scratch (zero-initialized at module load) ----------------
__device__ double g_stat[NSTAT];
__device__ u64    g_all[COUT * CSTR];

// the 16-channel conv+BN+relu+tanh core, shared by both block shapes
__device__ __forceinline__ void conv_core(const u64 e[CIN][3], const u64 o[CIN][3],
                                          float accA[2], float accB[2]) {
#pragma unroll 1
    for (int c = 0; c < COUT; c++) {
        const u64* w = &c_all[c * CSTR];      // warp-uniform -> LDCU/UR
        const u64 sh = w[NTAP];
#pragma unroll
        for (int i = 0; i < 2; i++) {
            u64 v0 = fma2(w[0], e[0][i], sh);     // shift folded into chain init
            v0 = fma2(w[1],  o[0][i],     v0);
            v0 = fma2(w[2],  e[0][i + 1], v0);
            v0 = fma2(w[3],  o[0][i + 1], v0);
            v0 = fma2(w[4],  e[1][i],     v0);
            v0 = fma2(w[5],  o[1][i],     v0);
            u64 v1 = mul2(w[6], e[1][i + 1]);
            v1 = fma2(w[7],  o[1][i + 1], v1);
            v1 = fma2(w[8],  e[2][i],     v1);
            v1 = fma2(w[9],  o[2][i],     v1);
            v1 = fma2(w[10], e[2][i + 1], v1);
            v1 = fma2(w[11], o[2][i + 1], v1);
            u64 v = add2(v0, v1);
            float lo, hi; up2(v, lo, hi);
            accA[i] += tha(fmaxf(lo, 0.f));
            accB[i] += tha(fmaxf(hi, 0.f));
        }
    }
}

// ---------------------------------------------------------------------------
// Kernel 1: tap sums + Gram matrix, v3: software-pipelined.
// Thread = column j; walks SROWS feat rows. Row r+2's taps are prefetched
// BEFORE the 102-FMA block on row r's window, hiding L2-hit latency.
// ---------------------------------------------------------------------------
__global__ void __launch_bounds__(256, 2) stats_kernel(const float* __restrict__ x) {
    float S[NTAP];
    float G[NTRI];
#pragma unroll
    for (int k = 0; k < NTAP; k++) S[k] = 0.f;
#pragma unroll
    for (int k = 0; k < NTRI; k++) G[k] = 0.f;

    const int j  = threadIdx.x;          // 0..255; active j < WF
    const int i0 = blockIdx.x * SROWS;
    const int nr = (i0 + SROWS <= HF) ? SROWS : (HF - i0);
    const float* xb = x + (size_t)blockIdx.y * CIN * HIN * WIN;

    if (j < WF) {
        const float* p0 = xb + (size_t)i0 * WIN + j;
        float t0[CIN], t1[CIN], b0[CIN], b1[CIN];
#pragma unroll
        for (int ci = 0; ci < CIN; ci++) {
            const float* p = p0 + (size_t)ci * HIN * WIN;
            t0[ci] = __ldg(p);
            t1[ci] = __ldg(p + 1);
            b0[ci] = __ldg(p + WIN);
            b1[ci] = __ldg(p + WIN + 1);
        }
        for (int r = 0; r < nr; r++) {
            // prefetch row i0+r+2 (clamped at image bottom; extra loads unused)
            const int pr = (i0 + r + 2 < HIN) ? (r + 2) : (HIN - 1 - i0);
            const float* pn = p0 + (size_t)pr * WIN;
            float n0[CIN], n1[CIN];
#pragma unroll
            for (int ci = 0; ci < CIN; ci++) {
                const float* p = pn + (size_t)ci * HIN * WIN;
                n0[ci] = __ldg(p);
                n1[ci] = __ldg(p + 1);
            }

            float xv[NTAP];
#pragma unroll
            for (int ci = 0; ci < CIN; ci++) {
                xv[ci * 4 + 0] = t0[ci];
                xv[ci * 4 + 1] = t1[ci];
                xv[ci * 4 + 2] = b0[ci];
                xv[ci * 4 + 3] = b1[ci];
            }
#pragma unroll
            for (int k = 0; k < NTAP; k++) {
                S[k] += xv[k];
#pragma unroll
                for (int l = 0; l <= k; l++)
                    G[k * (k + 1) / 2 + l] = fmaf(xv[k], xv[l], G[k * (k + 1) / 2 + l]);
            }
#pragma unroll
            for (int ci = 0; ci < CIN; ci++) {
                t0[ci] = b0[ci]; t1[ci] = b1[ci];
                b0[ci] = n0[ci]; b1[ci] = n1[ci];
            }
        }
    }

    const unsigned m = 0xffffffffu;
#pragma unroll
    for (int k = 0; k < NTAP; k++) {
        float a = S[k];
#pragma unroll
        for (int o = 16; o > 0; o >>= 1) a += __shfl_xor_sync(m, a, o);
        S[k] = a;
    }
#pragma unroll
    for (int k = 0; k < NTRI; k++) {
        float a = G[k];
#pragma unroll
        for (int o = 16; o > 0; o >>= 1) a += __shfl_xor_sync(m, a, o);
        G[k] = a;
    }

    __shared__ float red[8][NSTAT];
    const int warp = threadIdx.x >> 5, lane = threadIdx.x & 31;
    if (lane == 0) {
#pragma unroll
        for (int k = 0; k < NTAP; k++) red[warp][k] = S[k];
#pragma unroll
        for (int k = 0; k < NTRI; k++) red[warp][NTAP + k] = G[k];
    }
    __syncthreads();
    if (threadIdx.x < NSTAT) {
        float tot = 0.f;
#pragma unroll
        for (int w = 0; w < 8; w++) tot += red[w][threadIdx.x];
        atomicAdd(&g_stat[threadIdx.x], (double)tot);
    }
}

// ---------------------------------------------------------------------------
// Kernel 2: stage stats -> smem, re-zero g_stat (for next graph replay),
// reconstruct per-channel stats, fold BN (conv bias cancels).
// ---------------------------------------------------------------------------
__global__ void finalize_kernel(const float* __restrict__ w,
                                const float* __restrict__ gamma,
                                const float* __restrict__ beta) {
    __shared__ double st[NSTAT];
    const int t = threadIdx.x;
    if (t < NSTAT) st[t] = g_stat[t];
    __syncthreads();
    if (t < NSTAT) g_stat[t] = 0.0;

    if (t >= COUT) return;
    const int c = t;
    const double N = (double)NPIX;
    double wc[NTAP];
#pragma unroll
    for (int k = 0; k < NTAP; k++) wc[k] = (double)w[c * NTAP + k];

    double mean = 0.0;
#pragma unroll
    for (int k = 0; k < NTAP; k++) mean += wc[k] * st[k];
    mean /= N;

    double e2 = 0.0;
#pragma unroll
    for (int k = 0; k < NTAP; k++) {
#pragma unroll
        for (int l = 0; l <= k; l++) {
            double g = st[NTAP + k * (k + 1) / 2 + l];
            double tt = wc[k] * wc[l] * g;
            e2 += (l == k) ? tt : 2.0 * tt;
        }
    }
    e2 /= N;
    double var = e2 - mean * mean;
    float scale = gamma[c] * rsqrtf((float)var + BN_EPS);
    float shift = beta[c] - (float)mean * scale;
#pragma unroll
    for (int k = 0; k < NTAP; k++) {
        float ws = w[c * NTAP + k] * scale;
        g_all[c * CSTR + k] = pk2(ws, ws);
    }
    g_all[c * CSTR + NTAP] = pk2(shift, shift);
}

// ---------------------------------------------------------------------------
// Kernel 3: fused conv+BN+relu+tanh+window (R13 verbatim — proven).
//  by <  17 : main 62x15 output tile
//  by >= 17 : (bx==0) thin tile, pair-cols 124..127 x 128 feat rows
// ---------------------------------------------------------------------------
__global__ void __launch_bounds__(256, 4) fused_out_kernel(const float* __restrict__ x,
                                                           float* __restrict__ out) {
    __shared__ union {
        struct { u64 pe[CIN][17][33]; u64 st[16][33]; } m;   // main tile
        struct { u64 pe[CIN][129][5]; u64 st[128][4]; } t;   // thin tile
    } sm;

    const int tid = threadIdx.x;
    const int b   = blockIdx.z;
    const float* xb = x + (size_t)b * CIN * HIN * WIN;
    const float inv = 1.0f / (COUT * KSZ * KSZ);

    if (blockIdx.y < 17) {
        const int oy0 = blockIdx.y * 15;
        const int ox0 = blockIdx.x * 62;

        for (int idx = tid; idx < CIN * 17 * 33; idx += 256) {
            const int jc = idx % 33;
            const int t2 = idx / 33;
            const int r  = t2 % 17;
            const int ci = t2 / 17;
            const int gr = oy0 + r, gc = ox0 + 2 * jc;
            u64 v = 0ull;
            if (gr < HIN && gc < WIN)
                v = *(const u64*)&xb[(size_t)(ci * HIN + gr) * WIN + gc];
            sm.m.pe[ci][r][jc] = v;
        }
        __syncthreads();

        const int jp = tid & 31;
        const int r0 = (tid >> 5) * 2;

        u64 e[CIN][3], o[CIN][3];
#pragma unroll
        for (int ci = 0; ci < CIN; ci++) {
#pragma unroll
            for (int i = 0; i < 3; i++) {
                u64 ev = sm.m.pe[ci][r0 + i][jp];
                u64 en = sm.m.pe[ci][r0 + i][jp + 1];
                float elo, ehi, nlo, nhi;
                up2(ev, elo, ehi); up2(en, nlo, nhi);
                e[ci][i] = ev;
                o[ci][i] = pk2(ehi, nlo);
            }
        }

        float accA[2] = {0.f, 0.f}, accB[2] = {0.f, 0.f};
        conv_core(e, o, accA, accB);
        sm.m.st[r0 + 0][jp] = pk2(accA[0], accB[0]);
        sm.m.st[r0 + 1][jp] = pk2(accA[1], accB[1]);
        __syncthreads();

        const float* stf = (const float*)sm.m.st;
        for (int p = tid; p < 62 * 15; p += 256) {
            const int oy = p / 62, ox_ = p - oy * 62;
            const int oi = oy0 + oy, oj = ox0 + ox_;
            if (oi < HO) {
                const float* rp = stf + oy * 66 + ox_;
                out[(size_t)(b * HO + oi) * WO + oj] =
                    (rp[0] + rp[1] + rp[66] + rp[67]) * inv;
            }
        }
    } else {
        if (blockIdx.x != 0) return;
        const int oy0 = (blockIdx.y == 17) ? 0 : 127;

        for (int idx = tid; idx < CIN * 129 * 5; idx += 256) {
            const int jc = idx % 5;
            const int t2 = idx / 5;
            const int r  = t2 % 129;
            const int ci = t2 / 129;
            const int gr = oy0 + r, gc = 2 * (TPBASE + jc);
            u64 v = 0ull;
            if (gr < HIN && gc < WIN)
                v = *(const u64*)&xb[(size_t)(ci * HIN + gr) * WIN + gc];
            sm.t.pe[ci][r][jc] = v;
        }
        __syncthreads();

        const int jp = tid & 3;
        const int r0 = (tid >> 2) * 2;

        u64 e[CIN][3], o[CIN][3];
#pragma unroll
        for (int ci = 0; ci < CIN; ci++) {
#pragma unroll
            for (int i = 0; i < 3; i++) {
                u64 ev = sm.t.pe[ci][r0 + i][jp];
                u64 en = sm.t.pe[ci][r0 + i][jp + 1];
                float elo, ehi, nlo, nhi;
                up2(ev, elo, ehi); up2(en, nlo, nhi);
                e[ci][i] = ev;
                o[ci][i] = pk2(ehi, nlo);
            }
        }

        float accA[2] = {0.f, 0.f}, accB[2] = {0.f, 0.f};
        conv_core(e, o, accA, accB);
        sm.t.st[r0 + 0][jp] = pk2(accA[0], accB[0]);
        sm.t.st[r0 + 1][jp] = pk2(accA[1], accB[1]);
        __syncthreads();

        const float* stf = (const float*)sm.t.st;
        for (int p = tid; p < 6 * 127; p += 256) {
            const int ly = p / 6, ox_ = p - ly * 6;
            const int oi = oy0 + ly, oj = 2 * TPBASE + ox_;
            const float* rp = stf + ly * 8 + ox_;
            out[(size_t)(b * HO + oi) * WO + oj] =
                (rp[0] + rp[1] + rp[8] + rp[9]) * inv;
        }
    }
}

// ---------------------------------------------------------------------------
// kernel_launch: inputs: x, conv_w, conv_b (cancels under BN), gamma, beta
// ---------------------------------------------------------------------------
extern "C" void kernel_launch(void* const* d_in, const int* in_sizes, int n_in,
                              void* d_out, int out_size) {
    const float* x      = (const float*)d_in[0];
    const float* conv_w = (const float*)d_in[1];
    const float* gamma  = (const float*)d_in[3];
    const float* beta   = (const float*)d_in[4];
    float* out = (float*)d_out;

    void* p_all = 0;
    cudaGetSymbolAddress(&p_all, g_all);

    dim3 sgrid((HF + SROWS - 1) / SROWS, BATCH);   // 8 x 64
    stats_kernel<<<sgrid, 256>>>(x);
    finalize_kernel<<<1, 128>>>(conv_w, gamma, beta);
    cudaMemcpyToSymbolAsync(c_all, p_all, COUT * CSTR * sizeof(u64),
                            0, cudaMemcpyDeviceToDevice, 0);

    dim3 grid(4, 19, BATCH);   // y<17: main 62x15 tiles; y in {17,18}: thin tile
    fused_out_kernel<<<grid, 256>>>(x, out);
}

// round 15
// speedup vs baseline: 1.2693x; 1.0408x over previous
#include <cuda_runtime.h>

#define KSZ   2
#define CIN   3
#define COUT  16
#define HIN   256
#define WIN   256
#define HF    255
#define WF    255
#define HO    254
#define WO    254
#define BATCH 64
#define NPIX  (BATCH * HF * WF)
#define BN_EPS 1e-5f

#define NTAP  12
#define NTRI  78
#define NSTAT (NTAP + NTRI)
#define CSTR  13            // per-channel constant stride: 12 scaled weights + shift
#define SROWS 32            // feat rows per strip; block = 2 strips
#define TPBASE 124          // thin region: pair-columns 124..127 (feat cols 248..255)

typedef unsigned long long u64;

__device__ __forceinline__ u64 pk2(float lo, float hi) {
    u64 r; asm("mov.b64 %0,{%1,%2};" : "=l"(r) : "f"(lo), "f"(hi)); return r;
}
__device__ __forceinline__ void up2(u64 v, float& lo, float& hi) {
    asm("mov.b64 {%0,%1},%2;" : "=f"(lo), "=f"(hi) : "l"(v));
}
__device__ __forceinline__ u64 fma2(u64 a, u64 b, u64 c) {
    u64 d; asm("fma.rn.f32x2 %0,%1,%2,%3;" : "=l"(d) : "l"(a), "l"(b), "l"(c)); return d;
}
__device__ __forceinline__ u64 mul2(u64 a, u64 b) {
    u64 d; asm("mul.rn.f32x2 %0,%1,%2;" : "=l"(d) : "l"(a), "l"(b)); return d;
}
__device__ __forceinline__ u64 add2(u64 a, u64 b) {
    u64 d; asm("add.rn.f32x2 %0,%1,%2;" : "=l"(d) : "l"(a), "l"(b)); return d;
}
__device__ __forceinline__ float tha(float x) {
    float y; asm("tanh.approx.f32 %0,%1;" : "=f"(y) : "f"(x)); return y;
}

// ---------------- constant: per-channel [12 x packed w*scale, packed shift] ----------------
__constant__ u64 c_all[COUT * CSTR];

// ---------------- device scratch (zero-initialized at module load) ----------------
__device__ double g_stat[NSTAT];
__device__ u64    g_all[COUT * CSTR];

// the 16-channel conv+BN+relu+tanh core, shared by both block shapes
__device__ __forceinline__ void conv_core(const u64 e[CIN][3], const u64 o[CIN][3],
                                          float accA[2], float accB[2]) {
#pragma unroll 1
    for (int c = 0; c < COUT; c++) {
        const u64* w = &c_all[c * CSTR];      // warp-uniform -> LDCU/UR
        const u64 sh = w[NTAP];
#pragma unroll
        for (int i = 0; i < 2; i++) {
            u64 v0 = fma2(w[0], e[0][i], sh);     // shift folded into chain init
            v0 = fma2(w[1],  o[0][i],     v0);
            v0 = fma2(w[2],  e[0][i + 1], v0);
            v0 = fma2(w[3],  o[0][i + 1], v0);
            v0 = fma2(w[4],  e[1][i],     v0);
            v0 = fma2(w[5],  o[1][i],     v0);
            u64 v1 = mul2(w[6], e[1][i + 1]);
            v1 = fma2(w[7],  o[1][i + 1], v1);
            v1 = fma2(w[8],  e[2][i],     v1);
            v1 = fma2(w[9],  o[2][i],     v1);
            v1 = fma2(w[10], e[2][i + 1], v1);
            v1 = fma2(w[11], o[2][i + 1], v1);
            u64 v = add2(v0, v1);
            float lo, hi; up2(v, lo, hi);
            accA[i] += tha(fmaxf(lo, 0.f));
            accB[i] += tha(fmaxf(hi, 0.f));
        }
    }
}

// ---------------------------------------------------------------------------
// Kernel 1: tap sums + Gram matrix, v4: column-pair threads, single wave.
// Thread = pair p (feat cols 2p, 2p+1), strip s. Per row-iter: 6 loads
// (LDG.64 + LDG.32 per ci), 204 FMAs over 2 pixels; next row prefetched
// before the FMA block (load->use distance ~2x a 102-FMA body).
// Grid = 4 x 64 = 256 blocks = ONE wave at 2 CTAs/SM.
// ---------------------------------------------------------------------------
__global__ void __launch_bounds__(256, 2) stats_kernel(const float* __restrict__ x) {
    float S[NTAP];
    float G[NTRI];
#pragma unroll
    for (int k = 0; k < NTAP; k++) S[k] = 0.f;
#pragma unroll
    for (int k = 0; k < NTRI; k++) G[k] = 0.f;

    const int p  = threadIdx.x & 127;         // pair index 0..127
    const int s  = threadIdx.x >> 7;          // strip 0/1
    const int j  = 2 * p;                     // first feat col of the pair
    const int i0 = blockIdx.x * (2 * SROWS) + s * SROWS;
    const int nr = (i0 + SROWS <= HF) ? SROWS : (HF - i0);
    const bool has2 = (j + 1 < WF);           // pair (254,255): 2nd pixel invalid
    const float* xb = x + (size_t)blockIdx.y * CIN * HIN * WIN;

    {
        const float* p0 = xb + (size_t)i0 * WIN + j;
        float t[CIN][3], bt[CIN][3], n[CIN][3];
#pragma unroll
        for (int ci = 0; ci < CIN; ci++) {
            const float* q = p0 + (size_t)ci * HIN * WIN;
            float2 a = *(const float2*)q;
            float2 b = *(const float2*)(q + WIN);
            t[ci][0] = a.x;  t[ci][1] = a.y;
            t[ci][2] = has2 ? __ldg(q + 2) : 0.f;
            bt[ci][0] = b.x; bt[ci][1] = b.y;
            bt[ci][2] = has2 ? __ldg(q + WIN + 2) : 0.f;
        }
        for (int r = 0; r < nr; r++) {
            // prefetch row i0+r+2 (clamped at image bottom)
            const int pr = (i0 + r + 2 < HIN) ? (r + 2) : (HIN - 1 - i0);
            const float* pn = p0 + (size_t)pr * WIN;
#pragma unroll
            for (int ci = 0; ci < CIN; ci++) {
                const float* q = pn + (size_t)ci * HIN * WIN;
                float2 a = *(const float2*)q;
                n[ci][0] = a.x; n[ci][1] = a.y;
                n[ci][2] = has2 ? __ldg(q + 2) : 0.f;
            }

            // pixel 0: cols (j, j+1)
            float xv[NTAP];
#pragma unroll
            for (int ci = 0; ci < CIN; ci++) {
                xv[ci * 4 + 0] = t[ci][0];
                xv[ci * 4 + 1] = t[ci][1];
                xv[ci * 4 + 2] = bt[ci][0];
                xv[ci * 4 + 3] = bt[ci][1];
            }
#pragma unroll
            for (int k = 0; k < NTAP; k++) {
                S[k] += xv[k];
#pragma unroll
                for (int l = 0; l <= k; l++)
                    G[k * (k + 1) / 2 + l] = fmaf(xv[k], xv[l], G[k * (k + 1) / 2 + l]);
            }

            // pixel 1: cols (j+1, j+2) — predicated off for p == 127
            if (has2) {
                float yv[NTAP];
#pragma unroll
                for (int ci = 0; ci < CIN; ci++) {
                    yv[ci * 4 + 0] = t[ci][1];
                    yv[ci * 4 + 1] = t[ci][2];
                    yv[ci * 4 + 2] = bt[ci][1];
                    yv[ci * 4 + 3] = bt[ci][2];
                }
#pragma unroll
                for (int k = 0; k < NTAP; k++) {
                    S[k] += yv[k];
#pragma unroll
                    for (int l = 0; l <= k; l++)
                        G[k * (k + 1) / 2 + l] = fmaf(yv[k], yv[l], G[k * (k + 1) / 2 + l]);
                }
            }

#pragma unroll
            for (int ci = 0; ci < CIN; ci++) {
                t[ci][0] = bt[ci][0]; t[ci][1] = bt[ci][1]; t[ci][2] = bt[ci][2];
                bt[ci][0] = n[ci][0]; bt[ci][1] = n[ci][1]; bt[ci][2] = n[ci][2];
            }
        }
    }

    const unsigned m = 0xffffffffu;
#pragma unroll
    for (int k = 0; k < NTAP; k++) {
        float a = S[k];
#pragma unroll
        for (int o = 16; o > 0; o >>= 1) a += __shfl_xor_sync(m, a, o);
        S[k] = a;
    }
#pragma unroll
    for (int k = 0; k < NTRI; k++) {
        float a = G[k];
#pragma unroll
        for (int o = 16; o > 0; o >>= 1) a += __shfl_xor_sync(m, a, o);
        G[k] = a;
    }

    __shared__ float red[8][NSTAT];
    const int warp = threadIdx.x >> 5, lane = threadIdx.x & 31;
    if (lane == 0) {
#pragma unroll
        for (int k = 0; k < NTAP; k++) red[warp][k] = S[k];
#pragma unroll
        for (int k = 0; k < NTRI; k++) red[warp][NTAP + k] = G[k];
    }
    __syncthreads();
    if (threadIdx.x < NSTAT) {
        float tot = 0.f;
#pragma unroll
        for (int w = 0; w < 8; w++) tot += red[w][threadIdx.x];
        atomicAdd(&g_stat[threadIdx.x], (double)tot);
    }
}

// ---------------------------------------------------------------------------
// Kernel 2: stage stats -> smem, re-zero g_stat (for next graph replay),
// reconstruct per-channel stats, fold BN (conv bias cancels).
// ---------------------------------------------------------------------------
__global__ void finalize_kernel(const float* __restrict__ w,
                                const float* __restrict__ gamma,
                                const float* __restrict__ beta) {
    __shared__ double st[NSTAT];
    const int t = threadIdx.x;
    if (t < NSTAT) st[t] = g_stat[t];
    __syncthreads();
    if (t < NSTAT) g_stat[t] = 0.0;

    if (t >= COUT) return;
    const int c = t;
    const double N = (double)NPIX;
    double wc[NTAP];
#pragma unroll
    for (int k = 0; k < NTAP; k++) wc[k] = (double)w[c * NTAP + k];

    double mean = 0.0;
#pragma unroll
    for (int k = 0; k < NTAP; k++) mean += wc[k] * st[k];
    mean /= N;

    double e2 = 0.0;
#pragma unroll
    for (int k = 0; k < NTAP; k++) {
#pragma unroll
        for (int l = 0; l <= k; l++) {
            double g = st[NTAP + k * (k + 1) / 2 + l];
            double tt = wc[k] * wc[l] * g;
            e2 += (l == k) ? tt : 2.0 * tt;
        }
    }
    e2 /= N;
    double var = e2 - mean * mean;
    float scale = gamma[c] * rsqrtf((float)var + BN_EPS);
    float shift = beta[c] - (float)mean * scale;
#pragma unroll
    for (int k = 0; k < NTAP; k++) {
        float ws = w[c * NTAP + k] * scale;
        g_all[c * CSTR + k] = pk2(ws, ws);
    }
    g_all[c * CSTR + NTAP] = pk2(shift, shift);
}

// ---------------------------------------------------------------------------
// Kernel 3: fused conv+BN+relu+tanh+window (R13 verbatim — proven).
// ---------------------------------------------------------------------------
__global__ void __launch_bounds__(256, 4) fused_out_kernel(const float* __restrict__ x,
                                                           float* __restrict__ out) {
    __shared__ union {
        struct { u64 pe[CIN][17][33]; u64 st[16][33]; } m;   // main tile
        struct { u64 pe[CIN][129][5]; u64 st[128][4]; } t;   // thin tile
    } sm;

    const int tid = threadIdx.x;
    const int b   = blockIdx.z;
    const float* xb = x + (size_t)b * CIN * HIN * WIN;
    const float inv = 1.0f / (COUT * KSZ * KSZ);

    if (blockIdx.y < 17) {
        const int oy0 = blockIdx.y * 15;
        const int ox0 = blockIdx.x * 62;

        for (int idx = tid; idx < CIN * 17 * 33; idx += 256) {
            const int jc = idx % 33;
            const int t2 = idx / 33;
            const int r  = t2 % 17;
            const int ci = t2 / 17;
            const int gr = oy0 + r, gc = ox0 + 2 * jc;
            u64 v = 0ull;
            if (gr < HIN && gc < WIN)
                v = *(const u64*)&xb[(size_t)(ci * HIN + gr) * WIN + gc];
            sm.m.pe[ci][r][jc] = v;
        }
        __syncthreads();

        const int jp = tid & 31;
        const int r0 = (tid >> 5) * 2;

        u64 e[CIN][3], o[CIN][3];
#pragma unroll
        for (int ci = 0; ci < CIN; ci++) {
#pragma unroll
            for (int i = 0; i < 3; i++) {
                u64 ev = sm.m.pe[ci][r0 + i][jp];
                u64 en = sm.m.pe[ci][r0 + i][jp + 1];
                float elo, ehi, nlo, nhi;
                up2(ev, elo, ehi); up2(en, nlo, nhi);
                e[ci][i] = ev;
                o[ci][i] = pk2(ehi, nlo);
            }
        }

        float accA[2] = {0.f, 0.f}, accB[2] = {0.f, 0.f};
        conv_core(e, o, accA, accB);
        sm.m.st[r0 + 0][jp] = pk2(accA[0], accB[0]);
        sm.m.st[r0 + 1][jp] = pk2(accA[1], accB[1]);
        __syncthreads();

        const float* stf = (const float*)sm.m.st;
        for (int p = tid; p < 62 * 15; p += 256) {
            const int oy = p / 62, ox_ = p - oy * 62;
            const int oi = oy0 + oy, oj = ox0 + ox_;
            if (oi < HO) {
                const float* rp = stf + oy * 66 + ox_;
                out[(size_t)(b * HO + oi) * WO + oj] =
                    (rp[0] + rp[1] + rp[66] + rp[67]) * inv;
            }
        }
    } else {
        if (blockIdx.x != 0) return;
        const int oy0 = (blockIdx.y == 17) ? 0 : 127;

        for (int idx = tid; idx < CIN * 129 * 5; idx += 256) {
            const int jc = idx % 5;
            const int t2 = idx / 5;
            const int r  = t2 % 129;
            const int ci = t2 / 129;
            const int gr = oy0 + r, gc = 2 * (TPBASE + jc);
            u64 v = 0ull;
            if (gr < HIN && gc < WIN)
                v = *(const u64*)&xb[(size_t)(ci * HIN + gr) * WIN + gc];
            sm.t.pe[ci][r][jc] = v;
        }
        __syncthreads();

        const int jp = tid & 3;
        const int r0 = (tid >> 2) * 2;

        u64 e[CIN][3], o[CIN][3];
#pragma unroll
        for (int ci = 0; ci < CIN; ci++) {
#pragma unroll
            for (int i = 0; i < 3; i++) {
                u64 ev = sm.t.pe[ci][r0 + i][jp];
                u64 en = sm.t.pe[ci][r0 + i][jp + 1];
                float elo, ehi, nlo, nhi;
                up2(ev, elo, ehi); up2(en, nlo, nhi);
                e[ci][i] = ev;
                o[ci][i] = pk2(ehi, nlo);
            }
        }

        float accA[2] = {0.f, 0.f}, accB[2] = {0.f, 0.f};
        conv_core(e, o, accA, accB);
        sm.t.st[r0 + 0][jp] = pk2(accA[0], accB[0]);
        sm.t.st[r0 + 1][jp] = pk2(accA[1], accB[1]);
        __syncthreads();

        const float* stf = (const float*)sm.t.st;
        for (int p = tid; p < 6 * 127; p += 256) {
            const int ly = p / 6, ox_ = p - ly * 6;
            const int oi = oy0 + ly, oj = 2 * TPBASE + ox_;
            const float* rp = stf + ly * 8 + ox_;
            out[(size_t)(b * HO + oi) * WO + oj] =
                (rp[0] + rp[1] + rp[8] + rp[9]) * inv;
        }
    }
}

// ---------------------------------------------------------------------------
// kernel_launch: inputs: x, conv_w, conv_b (cancels under BN), gamma, beta
// ---------------------------------------------------------------------------
extern "C" void kernel_launch(void* const* d_in, const int* in_sizes, int n_in,
                              void* d_out, int out_size) {
    const float* x      = (const float*)d_in[0];
    const float* conv_w = (const float*)d_in[1];
    const float* gamma  = (const float*)d_in[3];
    const float* beta   = (const float*)d_in[4];
    float* out = (float*)d_out;

    void* p_all = 0;
    cudaGetSymbolAddress(&p_all, g_all);

    dim3 sgrid((HF + 2 * SROWS - 1) / (2 * SROWS), BATCH);   // 4 x 64 = 256 blocks
    stats_kernel<<<sgrid, 256>>>(x);
    finalize_kernel<<<1, 128>>>(conv_w, gamma, beta);
    cudaMemcpyToSymbolAsync(c_all, p_all, COUT * CSTR * sizeof(u64),
                            0, cudaMemcpyDeviceToDevice, 0);

    dim3 grid(4, 19, BATCH);   // y<17: main 62x15 tiles; y in {17,18}: thin tile
    fused_out_kernel<<<grid, 256>>>(x, out);
}